// round 6
// baseline (speedup 1.0000x reference)
#include <cuda_runtime.h>
#include <cstdint>

// SpatialTransformer bilinear grid sample — arithmetic model of the reference:
//   einsum -> fp32 SIMT GEMM (cuBLAS small-M / Eigen gebp): serial K-loop,
//             acc = rn(t0*x); acc = fma(t1,y,acc); acc = rn(t2 + acc)
//   pointwise -> separate fmul/fadd (no FMA contraction), left-associated
//             exactly as the Python source (confirmed helpful in R5).
//
// images: (16, 512, 512, 16) f32   theta: (16, 2, 3) f32   out: (B*H*W, C) f32
// Mapping: 1 thread per (pixel, channel-quad); 4 lanes/pixel -> 128B-coalesced
// gathers and stores.

#define ST_B 16
#define ST_H 512
#define ST_W 512
#define ST_C 16
#define ST_HW (ST_H * ST_W)
#define ST_LOG_W 9
#define ST_LOG_HW 18

__global__ __launch_bounds__(256, 8)
void st_bilinear_kernel(const float* __restrict__ images,
                        const float* __restrict__ theta,
                        float* __restrict__ out)
{
    const uint32_t tid = blockIdx.x * 256u + threadIdx.x;
    const uint32_t pix = tid >> 2;          // output pixel in [0, B*H*W)
    const uint32_t q   = tid & 3u;          // channel quad 0..3

    const uint32_t b  = pix >> ST_LOG_HW;
    const uint32_t yo = (pix >> ST_LOG_W) & (ST_H - 1);
    const uint32_t xo = pix & (ST_W - 1);

    const float* th = theta + b * 6;
    const float t00 = __ldg(th + 0), t01 = __ldg(th + 1), t02 = __ldg(th + 2);
    const float t10 = __ldg(th + 3), t11 = __ldg(th + 4), t12 = __ldg(th + 5);

    const float xof = (float)xo;
    const float yof = (float)yo;

    // --- einsum: fp32 serial-K FMA chain (acc starts at 0, k ascending) ----
    // acc = rn(t0*x); acc = rn(t1*y + acc); acc = rn(t2*1 + acc)
    float xn = __fadd_rn(__fmaf_rn(t01, yof, __fmul_rn(t00, xof)), t02);
    float yn = __fadd_rn(__fmaf_rn(t11, yof, __fmul_rn(t10, xof)), t12);

    // --- affine to pixel coords: 0.5*((x+1)*W - 1), separate rounded ops ---
    float x = __fmul_rn(0.5f, __fsub_rn(__fmul_rn(__fadd_rn(xn, 1.0f), (float)ST_W), 1.0f));
    float y = __fmul_rn(0.5f, __fsub_rn(__fmul_rn(__fadd_rn(yn, 1.0f), (float)ST_H), 1.0f));

    const int xf = (int)floorf(x);
    const int yf = (int)floorf(y);
    const int x0 = min(max(xf,     0), ST_W - 1);
    const int x1 = min(max(xf + 1, 0), ST_W - 1);
    const int y0 = min(max(yf,     0), ST_H - 1);
    const int y1 = min(max(yf + 1, 0), ST_H - 1);

    const float x0f = (float)x0, x1f = (float)x1;
    const float y0f = (float)y0, y1f = (float)y1;

    const float dx1 = __fsub_rn(x1f, x);
    const float dx0 = __fsub_rn(x, x0f);
    const float dy1 = __fsub_rn(y1f, y);
    const float dy0 = __fsub_rn(y, y0f);

    const float wa = __fmul_rn(dx1, dy1);  // * p00 (y0,x0)
    const float wb = __fmul_rn(dx1, dy0);  // * p01 (y1,x0)
    const float wc = __fmul_rn(dx0, dy1);  // * p10 (y0,x1)
    const float wd = __fmul_rn(dx0, dy0);  // * p11 (y1,x1)

    const float* img = images + ((size_t)b << ST_LOG_HW) * ST_C;
    const uint32_t co = q * 4u;

    const float4 p00 = __ldg((const float4*)(img + (((uint32_t)y0 << ST_LOG_W) + (uint32_t)x0) * ST_C + co));
    const float4 p01 = __ldg((const float4*)(img + (((uint32_t)y1 << ST_LOG_W) + (uint32_t)x0) * ST_C + co));
    const float4 p10 = __ldg((const float4*)(img + (((uint32_t)y0 << ST_LOG_W) + (uint32_t)x1) * ST_C + co));
    const float4 p11 = __ldg((const float4*)(img + (((uint32_t)y1 << ST_LOG_W) + (uint32_t)x1) * ST_C + co));

    // ((wa*p00 + wb*p01) + wc*p10) + wd*p11, every op individually rounded
    float4 r;
    r.x = __fadd_rn(__fadd_rn(__fadd_rn(__fmul_rn(wa, p00.x), __fmul_rn(wb, p01.x)),
                              __fmul_rn(wc, p10.x)), __fmul_rn(wd, p11.x));
    r.y = __fadd_rn(__fadd_rn(__fadd_rn(__fmul_rn(wa, p00.y), __fmul_rn(wb, p01.y)),
                              __fmul_rn(wc, p10.y)), __fmul_rn(wd, p11.y));
    r.z = __fadd_rn(__fadd_rn(__fadd_rn(__fmul_rn(wa, p00.z), __fmul_rn(wb, p01.z)),
                              __fmul_rn(wc, p10.z)), __fmul_rn(wd, p11.z));
    r.w = __fadd_rn(__fadd_rn(__fadd_rn(__fmul_rn(wa, p00.w), __fmul_rn(wb, p01.w)),
                              __fmul_rn(wc, p10.w)), __fmul_rn(wd, p11.w));

    *((float4*)(out + (size_t)pix * ST_C + co)) = r;
}

extern "C" void kernel_launch(void* const* d_in, const int* in_sizes, int n_in,
                              void* d_out, int out_size)
{
    const float* images = (const float*)d_in[0];
    const float* theta  = (const float*)d_in[1];
    if (n_in >= 2 && in_sizes[0] < in_sizes[1]) {   // theta is the 96-elem buffer
        images = (const float*)d_in[1];
        theta  = (const float*)d_in[0];
    }
    float* out = (float*)d_out;

    const uint32_t total  = (uint32_t)ST_B * ST_HW * 4u;
    const uint32_t blocks = total / 256u;
    st_bilinear_kernel<<<blocks, 256>>>(images, theta, out);
}

// round 9
// speedup vs baseline: 1.0254x; 1.0254x over previous
#include <cuda_runtime.h>
#include <cstdint>

// SpatialTransformer bilinear grid sample — bit-exact vs reference (R6: rel_err 0.0).
// Arithmetic locked: fp32 serial-K FMA-chain einsum, unfused pointwise.
//
// Perf change under test (3rd submit; two infra failures, never executed):
// ~75% of samples are border-clamped (theta ~ N(0,1e-4)); a clamped dim makes
// corner addresses identical. Load each DISTINCT corner once (~1.6 avg
// loads/pixel instead of 4) -> cuts L1 wavefronts, the 78%-binding pipe in R6.
//
// images: (16,512,512,16) f32   theta: (16,2,3) f32   out: (B*H*W, C) f32
// Mapping: 1 thread per (pixel, channel-quad); 4 lanes/pixel -> coalesced.

#define ST_B 16
#define ST_H 512
#define ST_W 512
#define ST_C 16
#define ST_HW (ST_H * ST_W)
#define ST_LOG_W 9
#define ST_LOG_HW 18

__global__ __launch_bounds__(256, 8)
void st_bilinear_kernel(const float* __restrict__ images,
                        const float* __restrict__ theta,
                        float* __restrict__ out)
{
    const uint32_t tid = blockIdx.x * 256u + threadIdx.x;
    const uint32_t pix = tid >> 2;          // output pixel in [0, B*H*W)
    const uint32_t q   = tid & 3u;          // channel quad 0..3

    const uint32_t b  = pix >> ST_LOG_HW;
    const uint32_t yo = (pix >> ST_LOG_W) & (ST_H - 1);
    const uint32_t xo = pix & (ST_W - 1);

    const float* th = theta + b * 6;
    const float t00 = __ldg(th + 0), t01 = __ldg(th + 1), t02 = __ldg(th + 2);
    const float t10 = __ldg(th + 3), t11 = __ldg(th + 4), t12 = __ldg(th + 5);

    const float xof = (float)xo;
    const float yof = (float)yo;

    // --- einsum: fp32 serial-K FMA chain (bit-exact, LOCKED) ---------------
    float xn = __fadd_rn(__fmaf_rn(t01, yof, __fmul_rn(t00, xof)), t02);
    float yn = __fadd_rn(__fmaf_rn(t11, yof, __fmul_rn(t10, xof)), t12);

    // --- affine to pixel coords: 0.5*((x+1)*W - 1), unfused (LOCKED) -------
    float x = __fmul_rn(0.5f, __fsub_rn(__fmul_rn(__fadd_rn(xn, 1.0f), (float)ST_W), 1.0f));
    float y = __fmul_rn(0.5f, __fsub_rn(__fmul_rn(__fadd_rn(yn, 1.0f), (float)ST_H), 1.0f));

    const int xf = (int)floorf(x);
    const int yf = (int)floorf(y);
    const int x0 = min(max(xf,     0), ST_W - 1);
    const int x1 = min(max(xf + 1, 0), ST_W - 1);
    const int y0 = min(max(yf,     0), ST_H - 1);
    const int y1 = min(max(yf + 1, 0), ST_H - 1);

    const float x0f = (float)x0, x1f = (float)x1;
    const float y0f = (float)y0, y1f = (float)y1;

    const float dx1 = __fsub_rn(x1f, x);
    const float dx0 = __fsub_rn(x, x0f);
    const float dy1 = __fsub_rn(y1f, y);
    const float dy0 = __fsub_rn(y, y0f);

    const float wa = __fmul_rn(dx1, dy1);  // * p00 (y0,x0)
    const float wb = __fmul_rn(dx1, dy0);  // * p01 (y1,x0)
    const float wc = __fmul_rn(dx0, dy1);  // * p10 (y0,x1)
    const float wd = __fmul_rn(dx0, dy0);  // * p11 (y1,x1)

    const float* img = images + ((size_t)b << ST_LOG_HW) * ST_C;
    const uint32_t co = q * 4u;

    // Base offset (floats) for corner (y0,x0); others derived by small adds.
    const uint32_t off00 = ((((uint32_t)y0 << ST_LOG_W) + (uint32_t)x0) << 4) + co;
    const bool lx = (x1 != x0);             // x not clamped-collapsed
    const bool ly = (y1 != y0);             // y not clamped-collapsed

    const float4 p00 = __ldg((const float4*)(img + off00));

    float4 p10 = p00;
    if (lx) p10 = __ldg((const float4*)(img + off00 + ST_C));            // +1 px in x

    float4 p01 = p00;
    if (ly) p01 = __ldg((const float4*)(img + off00 + (ST_W * ST_C)));   // +1 row

    float4 p11 = lx ? p10 : p01;            // collapsed reuse (bit-identical)
    if (lx && ly) p11 = __ldg((const float4*)(img + off00 + (ST_W * ST_C) + ST_C));

    // ((wa*p00 + wb*p01) + wc*p10) + wd*p11, every op individually rounded (LOCKED)
    float4 r;
    r.x = __fadd_rn(__fadd_rn(__fadd_rn(__fmul_rn(wa, p00.x), __fmul_rn(wb, p01.x)),
                              __fmul_rn(wc, p10.x)), __fmul_rn(wd, p11.x));
    r.y = __fadd_rn(__fadd_rn(__fadd_rn(__fmul_rn(wa, p00.y), __fmul_rn(wb, p01.y)),
                              __fmul_rn(wc, p10.y)), __fmul_rn(wd, p11.y));
    r.z = __fadd_rn(__fadd_rn(__fadd_rn(__fmul_rn(wa, p00.z), __fmul_rn(wb, p01.z)),
                              __fmul_rn(wc, p10.z)), __fmul_rn(wd, p11.z));
    r.w = __fadd_rn(__fadd_rn(__fadd_rn(__fmul_rn(wa, p00.w), __fmul_rn(wb, p01.w)),
                              __fmul_rn(wc, p10.w)), __fmul_rn(wd, p11.w));

    *((float4*)(out + (size_t)pix * ST_C + co)) = r;
}

extern "C" void kernel_launch(void* const* d_in, const int* in_sizes, int n_in,
                              void* d_out, int out_size)
{
    const float* images = (const float*)d_in[0];
    const float* theta  = (const float*)d_in[1];
    if (n_in >= 2 && in_sizes[0] < in_sizes[1]) {   // theta is the 96-elem buffer
        images = (const float*)d_in[1];
        theta  = (const float*)d_in[0];
    }
    float* out = (float*)d_out;

    const uint32_t total  = (uint32_t)ST_B * ST_HW * 4u;
    const uint32_t blocks = total / 256u;
    st_bilinear_kernel<<<blocks, 256>>>(images, theta, out);
}

// round 10
// speedup vs baseline: 1.1109x; 1.0834x over previous
#include <cuda_runtime.h>
#include <cstdint>

// SpatialTransformer bilinear grid sample — bit-exact vs reference (rel_err 0.0).
// LOCKED arithmetic: fp32 serial-K FMA-chain einsum, unfused pointwise, exact
// reference association. Do not modify the float sequence.
//
// R10: 2 pixels/thread (same batch, rows y and y+256) -> amortizes tid/theta
// overhead (issued instr/pixel ~-15%) and doubles per-thread ILP to lift the
// 72.6% issue ceiling. Distinct-corner conditional gathers retained (R9 win).
//
// images: (16,512,512,16) f32   theta: (16,2,3) f32   out: (B*H*W, C) f32
// Mapping: 4 lanes per pixel (one float4 channel-quad each) -> all gather and
// store streams stay 128B-coalesced; warp covers 8+8 pixels.

#define ST_B 16
#define ST_H 512
#define ST_W 512
#define ST_C 16
#define ST_HW (ST_H * ST_W)        // 262144
#define ST_HALF (ST_HW / 2)        // 131072 = 2^17
#define ST_LOG_W 9

// One pixel's full LOCKED pipeline: coords -> distinct-corner gathers -> interp.
__device__ __forceinline__ void st_pixel(
    const float* __restrict__ img,      // batch base
    float* __restrict__ outp,           // out + globalPix*16 + co
    float xof, float yof, uint32_t co,
    float t00, float t01, float t02, float t10, float t11, float t12)
{
    // einsum: fp32 serial-K FMA chain (LOCKED)
    float xn = __fadd_rn(__fmaf_rn(t01, yof, __fmul_rn(t00, xof)), t02);
    float yn = __fadd_rn(__fmaf_rn(t11, yof, __fmul_rn(t10, xof)), t12);

    // affine: 0.5*((x+1)*W - 1), unfused (LOCKED)
    float x = __fmul_rn(0.5f, __fsub_rn(__fmul_rn(__fadd_rn(xn, 1.0f), (float)ST_W), 1.0f));
    float y = __fmul_rn(0.5f, __fsub_rn(__fmul_rn(__fadd_rn(yn, 1.0f), (float)ST_H), 1.0f));

    const int xf = (int)floorf(x);
    const int yf = (int)floorf(y);
    const int x0 = min(max(xf,     0), ST_W - 1);
    const int x1 = min(max(xf + 1, 0), ST_W - 1);
    const int y0 = min(max(yf,     0), ST_H - 1);
    const int y1 = min(max(yf + 1, 0), ST_H - 1);

    const float x0f = (float)x0, x1f = (float)x1;
    const float y0f = (float)y0, y1f = (float)y1;

    const float dx1 = __fsub_rn(x1f, x);
    const float dx0 = __fsub_rn(x, x0f);
    const float dy1 = __fsub_rn(y1f, y);
    const float dy0 = __fsub_rn(y, y0f);

    const float wa = __fmul_rn(dx1, dy1);  // * p00 (y0,x0)
    const float wb = __fmul_rn(dx1, dy0);  // * p01 (y1,x0)
    const float wc = __fmul_rn(dx0, dy1);  // * p10 (y0,x1)
    const float wd = __fmul_rn(dx0, dy0);  // * p11 (y1,x1)

    const uint32_t off00 = ((((uint32_t)y0 << ST_LOG_W) + (uint32_t)x0) << 4) + co;
    const bool lx = (x1 != x0);
    const bool ly = (y1 != y0);

    const float4 p00 = __ldg((const float4*)(img + off00));

    float4 p10 = p00;
    if (lx) p10 = __ldg((const float4*)(img + off00 + ST_C));

    float4 p01 = p00;
    if (ly) p01 = __ldg((const float4*)(img + off00 + (ST_W * ST_C)));

    float4 p11 = lx ? p10 : p01;
    if (lx && ly) p11 = __ldg((const float4*)(img + off00 + (ST_W * ST_C) + ST_C));

    // ((wa*p00 + wb*p01) + wc*p10) + wd*p11, individually rounded (LOCKED)
    float4 r;
    r.x = __fadd_rn(__fadd_rn(__fadd_rn(__fmul_rn(wa, p00.x), __fmul_rn(wb, p01.x)),
                              __fmul_rn(wc, p10.x)), __fmul_rn(wd, p11.x));
    r.y = __fadd_rn(__fadd_rn(__fadd_rn(__fmul_rn(wa, p00.y), __fmul_rn(wb, p01.y)),
                              __fmul_rn(wc, p10.y)), __fmul_rn(wd, p11.y));
    r.z = __fadd_rn(__fadd_rn(__fadd_rn(__fmul_rn(wa, p00.z), __fmul_rn(wb, p01.z)),
                              __fmul_rn(wc, p10.z)), __fmul_rn(wd, p11.z));
    r.w = __fadd_rn(__fadd_rn(__fadd_rn(__fmul_rn(wa, p00.w), __fmul_rn(wb, p01.w)),
                              __fmul_rn(wc, p10.w)), __fmul_rn(wd, p11.w));

    *((float4*)outp) = r;
}

__global__ __launch_bounds__(256)
void st_bilinear_kernel(const float* __restrict__ images,
                        const float* __restrict__ theta,
                        float* __restrict__ out)
{
    const uint32_t tid  = blockIdx.x * 256u + threadIdx.x;
    const uint32_t pixA = tid >> 2;            // packed index over (b, y<256, x)
    const uint32_t q    = tid & 3u;
    const uint32_t co   = q * 4u;

    const uint32_t b   = pixA >> 17;           // ST_HALF = 2^17
    const uint32_t yoA = (pixA >> ST_LOG_W) & 255u;
    const uint32_t xo  = pixA & (ST_W - 1);
    const uint32_t yoB = yoA + 256u;

    // theta (b,2,3): 3x float2 (8B-aligned: b*24B)
    const float* th = theta + b * 6;
    const float2 ta = __ldg((const float2*)(th + 0));
    const float2 tb = __ldg((const float2*)(th + 2));
    const float2 tc = __ldg((const float2*)(th + 4));
    const float t00 = ta.x, t01 = ta.y, t02 = tb.x;
    const float t10 = tb.y, t11 = tc.x, t12 = tc.y;

    const float xof  = (float)xo;
    const float yofA = (float)yoA;
    const float yofB = (float)yoB;

    const float* img = images + (size_t)b * (ST_HW * ST_C);

    // global output pixel for A: b*HW + yoA*W + xo = pixA + b*HALF
    const uint32_t gpixA = pixA + (b << 17);
    float* outA = out + (size_t)gpixA * ST_C + co;
    float* outB = outA + (size_t)ST_HALF * ST_C;   // +256 rows

    st_pixel(img, outA, xof, yofA, co, t00, t01, t02, t10, t11, t12);
    st_pixel(img, outB, xof, yofB, co, t00, t01, t02, t10, t11, t12);
}

extern "C" void kernel_launch(void* const* d_in, const int* in_sizes, int n_in,
                              void* d_out, int out_size)
{
    const float* images = (const float*)d_in[0];
    const float* theta  = (const float*)d_in[1];
    if (n_in >= 2 && in_sizes[0] < in_sizes[1]) {   // theta is the 96-elem buffer
        images = (const float*)d_in[1];
        theta  = (const float*)d_in[0];
    }
    float* out = (float*)d_out;

    // threads = B * (HW/2) * 4 = 8,388,608 -> 32768 blocks of 256
    const uint32_t total  = (uint32_t)ST_B * ST_HALF * 4u;
    const uint32_t blocks = total / 256u;
    st_bilinear_kernel<<<blocks, 256>>>(images, theta, out);
}

// round 11
// speedup vs baseline: 1.1389x; 1.0252x over previous
#include <cuda_runtime.h>
#include <cstdint>

// SpatialTransformer bilinear grid sample — bit-exact vs reference (rel_err 0.0).
// LOCKED arithmetic: fp32 serial-K FMA-chain einsum, unfused pointwise, exact
// reference association. Do not modify the float sequence.
//
// R11: replace conditional-load if{} blocks (BSSY/BRA/BSYNC ~2+ instr/pixel)
// with predicated @q ld.global.nc.v4 (inline PTX, fallback-initialized regs),
// and FFLOOR+CVT -> single CVT.RMI. Pure issue-count surgery; values bit-identical.
//
// images: (16,512,512,16) f32   theta: (16,2,3) f32   out: (B*H*W, C) f32
// Mapping: 4 lanes/pixel (one float4 quad each), 2 pixels/thread (rows y, y+256).

#define ST_B 16
#define ST_H 512
#define ST_W 512
#define ST_C 16
#define ST_HW (ST_H * ST_W)        // 262144
#define ST_HALF (ST_HW / 2)        // 131072 = 2^17
#define ST_LOG_W 9

// Predicated 128-bit load: if pred, v = *p; else v keeps its init value.
// No branch instructions; predicated-off lanes generate no L1 traffic.
__device__ __forceinline__ void pld128(float4& v, const float* p, int pred) {
    asm("{\n\t"
        ".reg .pred q;\n\t"
        "setp.ne.s32 q, %5, 0;\n\t"
        "@q ld.global.nc.v4.f32 {%0,%1,%2,%3}, [%4];\n\t"
        "}"
        : "+f"(v.x), "+f"(v.y), "+f"(v.z), "+f"(v.w)
        : "l"(p), "r"(pred));
}

// One pixel's full LOCKED pipeline: coords -> distinct-corner gathers -> interp.
__device__ __forceinline__ void st_pixel(
    const float* __restrict__ img,      // batch base
    float* __restrict__ outp,           // out + globalPix*16 + co
    float xof, float yof, uint32_t co,
    float t00, float t01, float t02, float t10, float t11, float t12)
{
    // einsum: fp32 serial-K FMA chain (LOCKED)
    float xn = __fadd_rn(__fmaf_rn(t01, yof, __fmul_rn(t00, xof)), t02);
    float yn = __fadd_rn(__fmaf_rn(t11, yof, __fmul_rn(t10, xof)), t12);

    // affine: 0.5*((x+1)*W - 1), unfused (LOCKED)
    float x = __fmul_rn(0.5f, __fsub_rn(__fmul_rn(__fadd_rn(xn, 1.0f), (float)ST_W), 1.0f));
    float y = __fmul_rn(0.5f, __fsub_rn(__fmul_rn(__fadd_rn(yn, 1.0f), (float)ST_H), 1.0f));

    // (int)floorf(x) == __float2int_rd(x) for our range; single CVT.RMI
    const int xf = __float2int_rd(x);
    const int yf = __float2int_rd(y);
    const int x0 = min(max(xf,     0), ST_W - 1);
    const int x1 = min(max(xf + 1, 0), ST_W - 1);
    const int y0 = min(max(yf,     0), ST_H - 1);
    const int y1 = min(max(yf + 1, 0), ST_H - 1);

    const float x0f = (float)x0, x1f = (float)x1;
    const float y0f = (float)y0, y1f = (float)y1;

    const float dx1 = __fsub_rn(x1f, x);
    const float dx0 = __fsub_rn(x, x0f);
    const float dy1 = __fsub_rn(y1f, y);
    const float dy0 = __fsub_rn(y, y0f);

    const float wa = __fmul_rn(dx1, dy1);  // * p00 (y0,x0)
    const float wb = __fmul_rn(dx1, dy0);  // * p01 (y1,x0)
    const float wc = __fmul_rn(dx0, dy1);  // * p10 (y0,x1)
    const float wd = __fmul_rn(dx0, dy0);  // * p11 (y1,x1)

    const uint32_t off00 = ((((uint32_t)y0 << ST_LOG_W) + (uint32_t)x0) << 4) + co;
    const int lx = (x1 != x0);
    const int ly = (y1 != y0);

    const float4 p00 = __ldg((const float4*)(img + off00));

    float4 p10 = p00;                      // fallback when x collapsed
    pld128(p10, img + off00 + ST_C, lx);

    float4 p01 = p00;                      // fallback when y collapsed
    pld128(p01, img + off00 + (ST_W * ST_C), ly);

    float4 p11 = lx ? p10 : p01;           // collapsed reuse (bit-identical)
    pld128(p11, img + off00 + (ST_W * ST_C) + ST_C, lx & ly);

    // ((wa*p00 + wb*p01) + wc*p10) + wd*p11, individually rounded (LOCKED)
    float4 r;
    r.x = __fadd_rn(__fadd_rn(__fadd_rn(__fmul_rn(wa, p00.x), __fmul_rn(wb, p01.x)),
                              __fmul_rn(wc, p10.x)), __fmul_rn(wd, p11.x));
    r.y = __fadd_rn(__fadd_rn(__fadd_rn(__fmul_rn(wa, p00.y), __fmul_rn(wb, p01.y)),
                              __fmul_rn(wc, p10.y)), __fmul_rn(wd, p11.y));
    r.z = __fadd_rn(__fadd_rn(__fadd_rn(__fmul_rn(wa, p00.z), __fmul_rn(wb, p01.z)),
                              __fmul_rn(wc, p10.z)), __fmul_rn(wd, p11.z));
    r.w = __fadd_rn(__fadd_rn(__fadd_rn(__fmul_rn(wa, p00.w), __fmul_rn(wb, p01.w)),
                              __fmul_rn(wc, p10.w)), __fmul_rn(wd, p11.w));

    *((float4*)outp) = r;
}

__global__ __launch_bounds__(256)
void st_bilinear_kernel(const float* __restrict__ images,
                        const float* __restrict__ theta,
                        float* __restrict__ out)
{
    const uint32_t tid  = blockIdx.x * 256u + threadIdx.x;
    const uint32_t pixA = tid >> 2;            // packed index over (b, y<256, x)
    const uint32_t q    = tid & 3u;
    const uint32_t co   = q * 4u;

    const uint32_t b   = pixA >> 17;           // ST_HALF = 2^17
    const uint32_t yoA = (pixA >> ST_LOG_W) & 255u;
    const uint32_t xo  = pixA & (ST_W - 1);
    const uint32_t yoB = yoA + 256u;

    // theta (b,2,3): 3x float2 (8B-aligned: b*24B)
    const float* th = theta + b * 6;
    const float2 ta = __ldg((const float2*)(th + 0));
    const float2 tb = __ldg((const float2*)(th + 2));
    const float2 tc = __ldg((const float2*)(th + 4));
    const float t00 = ta.x, t01 = ta.y, t02 = tb.x;
    const float t10 = tb.y, t11 = tc.x, t12 = tc.y;

    const float xof  = (float)xo;
    const float yofA = (float)yoA;
    const float yofB = (float)yoB;

    const float* img = images + (size_t)b * (ST_HW * ST_C);

    // global output pixel for A: b*HW + yoA*W + xo = pixA + b*HALF
    const uint32_t gpixA = pixA + (b << 17);
    float* outA = out + (size_t)gpixA * ST_C + co;
    float* outB = outA + (size_t)ST_HALF * ST_C;   // +256 rows

    st_pixel(img, outA, xof, yofA, co, t00, t01, t02, t10, t11, t12);
    st_pixel(img, outB, xof, yofB, co, t00, t01, t02, t10, t11, t12);
}

extern "C" void kernel_launch(void* const* d_in, const int* in_sizes, int n_in,
                              void* d_out, int out_size)
{
    const float* images = (const float*)d_in[0];
    const float* theta  = (const float*)d_in[1];
    if (n_in >= 2 && in_sizes[0] < in_sizes[1]) {   // theta is the 96-elem buffer
        images = (const float*)d_in[1];
        theta  = (const float*)d_in[0];
    }
    float* out = (float*)d_out;

    // threads = B * (HW/2) * 4 = 8,388,608 -> 32768 blocks of 256
    const uint32_t total  = (uint32_t)ST_B * ST_HALF * 4u;
    const uint32_t blocks = total / 256u;
    st_bilinear_kernel<<<blocks, 256>>>(images, theta, out);
}